// round 15
// baseline (speedup 1.0000x reference)
#include <cuda_runtime.h>
#include <cuda_fp16.h>
#include <cstdint>

// Problem constants (fixed by the dataset)
#define N_MAX   100000
#define E_MAX   1600000
#define ROW     128        // xl(64) | xr(64) halves per node
#define HC      64         // HEADS * OUT_CH
#define OUTC    32
#define SCAN_BS 1024
#define NBLK_MAX ((N_MAX + SCAN_BS - 1) / SCAN_BS)   // 98

// -------- scratch (static device globals; no allocation) --------
__device__ __align__(128) __half g_xlr[(size_t)N_MAX * ROW];    // 25.6 MB (fp16)
__device__ __align__(128) int   g_deg[N_MAX];
__device__ __align__(128) int   g_off[N_MAX + 1];
__device__ __align__(128) int   g_cur[N_MAX];
__device__ __align__(128) int   g_src[E_MAX];
__device__ __align__(128) int   g_blk[NBLK_MAX + 1];
__device__ int g_is64;   // 1 if edge_index is int64, 0 if int32

// ---------------- helpers ----------------
__device__ __forceinline__ float lrelu(float x) { return (x > 0.f) ? x : 0.2f * x; }

__device__ __forceinline__ uint32_t smem_u32(const void* p) {
    return (uint32_t)__cvta_generic_to_shared(p);
}
__device__ __forceinline__ void ldmatrix_x4(uint32_t& r0, uint32_t& r1, uint32_t& r2, uint32_t& r3, uint32_t addr) {
    asm volatile("ldmatrix.sync.aligned.m8n8.x4.shared.b16 {%0,%1,%2,%3}, [%4];"
                 : "=r"(r0), "=r"(r1), "=r"(r2), "=r"(r3) : "r"(addr));
}
__device__ __forceinline__ void ldmatrix_x4_trans(uint32_t& r0, uint32_t& r1, uint32_t& r2, uint32_t& r3, uint32_t addr) {
    asm volatile("ldmatrix.sync.aligned.m8n8.x4.trans.shared.b16 {%0,%1,%2,%3}, [%4];"
                 : "=r"(r0), "=r"(r1), "=r"(r2), "=r"(r3) : "r"(addr));
}
__device__ __forceinline__ void mma_16816(float* c, uint32_t a0, uint32_t a1, uint32_t a2, uint32_t a3,
                                          uint32_t b0, uint32_t b1) {
    asm volatile("mma.sync.aligned.m16n8k16.row.col.f32.f16.f16.f32 "
                 "{%0,%1,%2,%3},{%4,%5,%6,%7},{%8,%9},{%0,%1,%2,%3};"
                 : "+f"(c[0]), "+f"(c[1]), "+f"(c[2]), "+f"(c[3])
                 : "r"(a0), "r"(a1), "r"(a2), "r"(a3), "r"(b0), "r"(b1));
}

__device__ __forceinline__ void load_edge(const void* ei, int E, int ec, int& j, int& i) {
    if (g_is64) {
        const long long* p = (const long long*)ei;
        j = (int)p[ec]; i = (int)p[(size_t)E + ec];
    } else {
        const int* p = (const int*)ei;
        j = p[ec]; i = p[(size_t)E + ec];
    }
}

// ---------------- kernel 0: fused detect-dtype + zero degrees ----------------
__global__ void k_init(const void* ei, int N) {
    int idx = blockIdx.x * blockDim.x + threadIdx.x;
    if (idx < N) g_deg[idx] = 0;
    if (blockIdx.x == 0 && threadIdx.x < 32) {
        const long long* p = (const long long*)ei;
        long long v = p[threadIdx.x];
        bool ok = (v >= 0 && v < (long long)N);
        unsigned m = __ballot_sync(0xffffffffu, ok);
        if (threadIdx.x == 0) g_is64 = (m == 0xffffffffu) ? 1 : 0;
    }
}

// ---------------- kernel 1: FUSED tensor-core GEMM + edge histogram ----------------
#define A_STRIDE 40    // halves per row (80B, conflict-free ldmatrix)
#define W_STRIDE 136   // halves per row (272B, conflict-free ldmatrix.trans)
__global__ void __launch_bounds__(256) k_gemm_hist(
    const float* __restrict__ x, const float* __restrict__ Wl,
    const float* __restrict__ bl, const float* __restrict__ Wr,
    const float* __restrict__ br, const void* __restrict__ ei,
    int N, int E, int GB)
{
    if (blockIdx.x >= GB) {
        int base = (blockIdx.x - GB) * 1024 + threadIdx.x;
        #pragma unroll
        for (int q = 0; q < 4; q++) {
            int e = base + q * 256;
            if (e < E) {
                int j, i;
                load_edge(ei, E, e, j, i);
                atomicAdd(&g_deg[i], 1);
            }
        }
        return;
    }

    __shared__ __align__(16) __half As[128][A_STRIDE];
    __shared__ __align__(16) __half Ws[32][W_STRIDE];
    __shared__ float bcat[128];

    const int tid = threadIdx.x;
    const int warp = tid >> 5;
    const int lane = tid & 31;
    const int blockM = blockIdx.x * 128;

    if (tid < 128) bcat[tid] = (tid < HC) ? bl[tid] : br[tid - HC];

    float acc[16][4];
    #pragma unroll
    for (int nt = 0; nt < 16; nt++)
        #pragma unroll
        for (int q = 0; q < 4; q++) acc[nt][q] = 0.f;

    for (int k0 = 0; k0 < 128; k0 += 32) {
        #pragma unroll
        for (int it = 0; it < 4; it++) {
            int idx = it * 256 + tid;
            int row = idx >> 3;
            int c4  = (idx & 7) * 4;
            int gm = blockM + row;
            float4 v = make_float4(0.f, 0.f, 0.f, 0.f);
            if (gm < N) v = *reinterpret_cast<const float4*>(&x[(size_t)gm * 128 + k0 + c4]);
            *reinterpret_cast<__half2*>(&As[row][c4])     = __floats2half2_rn(v.x, v.y);
            *reinterpret_cast<__half2*>(&As[row][c4 + 2]) = __floats2half2_rn(v.z, v.w);
        }
        #pragma unroll
        for (int it = 0; it < 4; it++) {
            int idx = it * 256 + tid;
            int kk = idx >> 5;
            int c4 = (idx & 31) * 4;
            int gk = k0 + kk;
            float4 v = (c4 < HC)
                ? *reinterpret_cast<const float4*>(&Wl[(size_t)gk * HC + c4])
                : *reinterpret_cast<const float4*>(&Wr[(size_t)gk * HC + (c4 - HC)]);
            *reinterpret_cast<__half2*>(&Ws[kk][c4])     = __floats2half2_rn(v.x, v.y);
            *reinterpret_cast<__half2*>(&Ws[kk][c4 + 2]) = __floats2half2_rn(v.z, v.w);
        }
        __syncthreads();

        #pragma unroll
        for (int ks = 0; ks < 32; ks += 16) {
            uint32_t a0, a1, a2, a3;
            {
                int g = lane >> 3, r = lane & 7;
                int arow = warp * 16 + ((g & 1) ? 8 : 0) + r;
                int acol = ks + ((g & 2) ? 8 : 0);
                ldmatrix_x4(a0, a1, a2, a3, smem_u32(&As[arow][acol]));
            }
            #pragma unroll
            for (int p = 0; p < 8; p++) {
                int g = lane >> 3, r = lane & 7;
                int krow = ks + ((g & 1) ? 8 : 0) + r;
                int ncol = p * 16 + ((g & 2) ? 8 : 0);
                uint32_t b0, b1, b2, b3;
                ldmatrix_x4_trans(b0, b1, b2, b3, smem_u32(&Ws[krow][ncol]));
                mma_16816(acc[2 * p],     a0, a1, a2, a3, b0, b1);
                mma_16816(acc[2 * p + 1], a0, a1, a2, a3, b2, b3);
            }
        }
        __syncthreads();
    }

    const int crow0 = blockM + warp * 16 + (lane >> 2);
    const int ccol0 = 2 * (lane & 3);
    #pragma unroll
    for (int nt = 0; nt < 16; nt++) {
        int col = nt * 8 + ccol0;
        float bx = bcat[col], by = bcat[col + 1];
        if (crow0 < N)
            *reinterpret_cast<__half2*>(&g_xlr[(size_t)crow0 * ROW + col]) =
                __floats2half2_rn(acc[nt][0] + bx, acc[nt][1] + by);
        if (crow0 + 8 < N)
            *reinterpret_cast<__half2*>(&g_xlr[(size_t)(crow0 + 8) * ROW + col]) =
                __floats2half2_rn(acc[nt][2] + bx, acc[nt][3] + by);
    }
}

// --- two-level exclusive scan (proven) ---
__global__ void __launch_bounds__(SCAN_BS) kA_scan_local(int N) {
    __shared__ int wt[SCAN_BS / 32];
    const int tid = threadIdx.x, lane = tid & 31, wid = tid >> 5;
    int idx = blockIdx.x * SCAN_BS + tid;
    int v = (idx < N) ? g_deg[idx] : 0;
    int s = v;
    #pragma unroll
    for (int m = 1; m < 32; m <<= 1) {
        int o = __shfl_up_sync(0xffffffffu, s, m);
        if (lane >= m) s += o;
    }
    if (lane == 31) wt[wid] = s;
    __syncthreads();
    if (wid == 0) {
        int w = wt[lane];
        int ws = w;
        #pragma unroll
        for (int m = 1; m < 32; m <<= 1) {
            int o = __shfl_up_sync(0xffffffffu, ws, m);
            if (lane >= m) ws += o;
        }
        wt[lane] = ws - w;   // exclusive warp offsets
    }
    __syncthreads();
    int excl = (s - v) + wt[wid];
    if (idx < N) g_off[idx] = excl;
    if (tid == SCAN_BS - 1) g_blk[blockIdx.x] = excl + v;   // block total
}

__global__ void __launch_bounds__(128) kB_scan_blk(int NB, int N) {
    __shared__ int wt[4];
    const int tid = threadIdx.x, lane = tid & 31, wid = tid >> 5;
    int v = (tid < NB) ? g_blk[tid] : 0;
    int s = v;
    #pragma unroll
    for (int m = 1; m < 32; m <<= 1) {
        int o = __shfl_up_sync(0xffffffffu, s, m);
        if (lane >= m) s += o;
    }
    if (lane == 31) wt[wid] = s;
    __syncthreads();
    if (tid == 0) {
        int c = 0;
        #pragma unroll
        for (int q = 0; q < 4; q++) { int t = wt[q]; wt[q] = c; c += t; }
    }
    __syncthreads();
    int excl = (s - v) + wt[wid];
    if (tid < NB) g_blk[tid] = excl;
    if (tid == NB - 1) g_off[N] = excl + v;
}

__global__ void kC_add(int N) {
    int idx = blockIdx.x * blockDim.x + threadIdx.x;
    if (idx < N) {
        int o = g_off[idx] + g_blk[idx >> 10];
        g_off[idx] = o;
        g_cur[idx] = o;
    }
}

__global__ void k_scatter(const void* __restrict__ ei, int E, int N) {
    int e = blockIdx.x * blockDim.x + threadIdx.x;
    if (e >= E) return;
    int j, i;
    load_edge(ei, E, e, j, i);
    int pos = atomicAdd(&g_cur[i], 1);
    g_src[pos] = j;
}

// ---------------- kernel 2: per-node aggregation (warp per dst node, 4 edges/iter) ----------------
// Lane layout: lanes [8g, 8g+8) = edge slot g (g=0..3); within a slot, lane el (0..7)
// covers channels 8*el..8*el+7 (el 0-3 = head 0, el 4-7 = head 1).
// Score reduce = 2-shfl butterfly within the 4-lane head group.
__global__ void __launch_bounds__(256) k_agg(
    const float* __restrict__ att, const float* __restrict__ bias,
    float* __restrict__ out, int N)
{
    const int warp = (blockIdx.x * 256 + threadIdx.x) >> 5;
    const int lane = threadIdx.x & 31;
    if (warp >= N) return;
    const int i = warp;

    const int eg = lane >> 3;          // edge slot 0..3
    const int el = lane & 7;           // lane within edge
    const int cb = el * 8;             // channel base 0..56

    uint4 bx = *reinterpret_cast<const uint4*>(g_xlr + (size_t)i * ROW + HC + cb);
    float2 bb[4];
    bb[0] = __half22float2(reinterpret_cast<const __half2*>(&bx)[0]);
    bb[1] = __half22float2(reinterpret_cast<const __half2*>(&bx)[1]);
    bb[2] = __half22float2(reinterpret_cast<const __half2*>(&bx)[2]);
    bb[3] = __half22float2(reinterpret_cast<const __half2*>(&bx)[3]);
    float4 t0 = *reinterpret_cast<const float4*>(&att[cb]);
    float4 t1 = *reinterpret_cast<const float4*>(&att[cb + 4]);

    float acc[8];
    #pragma unroll
    for (int k = 0; k < 8; k++) acc[k] = 0.f;
    float d = 0.f;

    auto proc = [&](uint4 ax, bool valid) {
        float2 aa[4];
        aa[0] = __half22float2(reinterpret_cast<const __half2*>(&ax)[0]);
        aa[1] = __half22float2(reinterpret_cast<const __half2*>(&ax)[1]);
        aa[2] = __half22float2(reinterpret_cast<const __half2*>(&ax)[2]);
        aa[3] = __half22float2(reinterpret_cast<const __half2*>(&ax)[3]);
        float s = t0.x * lrelu(aa[0].x + bb[0].x) + t0.y * lrelu(aa[0].y + bb[0].y)
                + t0.z * lrelu(aa[1].x + bb[1].x) + t0.w * lrelu(aa[1].y + bb[1].y)
                + t1.x * lrelu(aa[2].x + bb[2].x) + t1.y * lrelu(aa[2].y + bb[2].y)
                + t1.z * lrelu(aa[3].x + bb[3].x) + t1.w * lrelu(aa[3].y + bb[3].y);
        s += __shfl_xor_sync(0xffffffffu, s, 1);
        s += __shfl_xor_sync(0xffffffffu, s, 2);
        float p = valid ? __expf(s) : 0.f;
        acc[0] += p * aa[0].x; acc[1] += p * aa[0].y;
        acc[2] += p * aa[1].x; acc[3] += p * aa[1].y;
        acc[4] += p * aa[2].x; acc[5] += p * aa[2].y;
        acc[6] += p * aa[3].x; acc[7] += p * aa[3].y;
        d += p;
    };

    // self loop in slot 0
    {
        uint4 ax = *reinterpret_cast<const uint4*>(g_xlr + (size_t)i * ROW + cb);
        proc(ax, eg == 0);
    }

    const int off = g_off[i];
    const int deg = g_deg[i];

    for (int tb = 0; tb < deg; tb += 32) {
        int cnt = deg - tb; if (cnt > 32) cnt = 32;
        int mysrc = (tb + lane < deg) ? g_src[off + tb + lane] : 0;

        int i0 = (eg < cnt) ? eg : 0;
        int jc = __shfl_sync(0xffffffffu, mysrc, i0);
        uint4 vcur = *reinterpret_cast<const uint4*>(g_xlr + (size_t)jc * ROW + cb);

        for (int u = 0; u < cnt; u += 4) {
            uint4 vnext = vcur;
            if (u + 4 < cnt) {
                int idxn = u + 4 + eg;
                int jn = __shfl_sync(0xffffffffu, mysrc, (idxn < cnt) ? idxn : 0);
                vnext = *reinterpret_cast<const uint4*>(g_xlr + (size_t)jn * ROW + cb);
            }
            proc(vcur, (u + eg) < cnt);
            vcur = vnext;
        }
    }

    // merge 4 edge slots (xor 8, xor 16)
    #pragma unroll
    for (int k = 0; k < 8; k++) {
        acc[k] += __shfl_xor_sync(0xffffffffu, acc[k], 8);
        acc[k] += __shfl_xor_sync(0xffffffffu, acc[k], 16);
    }
    d += __shfl_xor_sync(0xffffffffu, d, 8);
    d += __shfl_xor_sync(0xffffffffu, d, 16);

    float invd = 1.f / (d + 1e-16f);
    float o[8];
    #pragma unroll
    for (int k = 0; k < 8; k++) {
        float vk = acc[k] * invd;
        o[k] = 0.5f * (vk + __shfl_xor_sync(0xffffffffu, vk, 4));  // head merge
    }

    if (lane < 4) {   // eg==0, el<4: head-0 lanes hold merged out channels cb..cb+7
        float4 bi0 = *reinterpret_cast<const float4*>(&bias[cb]);
        float4 bi1 = *reinterpret_cast<const float4*>(&bias[cb + 4]);
        float r[8];
        r[0] = o[0] + bi0.x; r[1] = o[1] + bi0.y; r[2] = o[2] + bi0.z; r[3] = o[3] + bi0.w;
        r[4] = o[4] + bi1.x; r[5] = o[5] + bi1.y; r[6] = o[6] + bi1.z; r[7] = o[7] + bi1.w;
        #pragma unroll
        for (int k = 0; k < 8; k++) r[k] = r[k] / (1.f + expf(-r[k]));
        *reinterpret_cast<float4*>(&out[(size_t)i * OUTC + cb])     = make_float4(r[0], r[1], r[2], r[3]);
        *reinterpret_cast<float4*>(&out[(size_t)i * OUTC + cb + 4]) = make_float4(r[4], r[5], r[6], r[7]);
    }
}

// ---------------- launch ----------------
extern "C" void kernel_launch(void* const* d_in, const int* in_sizes, int n_in,
                              void* d_out, int out_size) {
    const float* x    = (const float*)d_in[0];
    const float* Wl   = (const float*)d_in[1];
    const float* bl   = (const float*)d_in[2];
    const float* Wr   = (const float*)d_in[3];
    const float* br   = (const float*)d_in[4];
    const float* att  = (const float*)d_in[5];
    const float* bias = (const float*)d_in[6];
    const void*  ei   = (const void*)d_in[7];
    float* out = (float*)d_out;

    int N = in_sizes[0] / 128;   // 100000
    int E = in_sizes[7] / 2;     // 1600000
    int NB = (N + SCAN_BS - 1) / SCAN_BS;   // 98
    int GB = (N + 127) / 128;               // GEMM blocks
    int HB = (E + 1023) / 1024;             // histogram blocks

    k_init<<<(N + 255) / 256, 256>>>(ei, N);
    k_gemm_hist<<<GB + HB, 256>>>(x, Wl, bl, Wr, br, ei, N, E, GB);
    kA_scan_local<<<NB, SCAN_BS>>>(N);
    kB_scan_blk<<<1, 128>>>(NB, N);
    kC_add<<<(N + 255) / 256, 256>>>(N);
    k_scatter<<<(E + 255) / 256, 256>>>(ei, E, N);
    k_agg<<<(N * 32 + 255) / 256, 256>>>(att, bias, out, N);
}

// round 17
// speedup vs baseline: 1.0250x; 1.0250x over previous
#include <cuda_runtime.h>
#include <cuda_fp16.h>
#include <cstdint>

// Problem constants (fixed by the dataset)
#define N_MAX   100000
#define E_MAX   1600000
#define ROW     128        // xl(64) | xr(64) halves per node
#define HC      64         // HEADS * OUT_CH
#define OUTC    32
#define SCAN_BS 1024
#define NBLK_MAX ((N_MAX + SCAN_BS - 1) / SCAN_BS)   // 98

// -------- scratch (static device globals; no allocation) --------
__device__ __align__(128) __half g_xlr[(size_t)N_MAX * ROW];    // 25.6 MB (fp16)
__device__ __align__(128) int   g_deg[N_MAX];
__device__ __align__(128) int   g_off[N_MAX + 1];
__device__ __align__(128) int   g_cur[N_MAX];
__device__ __align__(128) int   g_src[E_MAX];
__device__ __align__(128) int   g_blk[NBLK_MAX + 1];
__device__ int g_is64;   // 1 if edge_index is int64, 0 if int32

// ---------------- helpers ----------------
__device__ __forceinline__ float lrelu(float x) { return (x > 0.f) ? x : 0.2f * x; }

__device__ __forceinline__ uint32_t smem_u32(const void* p) {
    return (uint32_t)__cvta_generic_to_shared(p);
}
__device__ __forceinline__ void ldmatrix_x4(uint32_t& r0, uint32_t& r1, uint32_t& r2, uint32_t& r3, uint32_t addr) {
    asm volatile("ldmatrix.sync.aligned.m8n8.x4.shared.b16 {%0,%1,%2,%3}, [%4];"
                 : "=r"(r0), "=r"(r1), "=r"(r2), "=r"(r3) : "r"(addr));
}
__device__ __forceinline__ void ldmatrix_x4_trans(uint32_t& r0, uint32_t& r1, uint32_t& r2, uint32_t& r3, uint32_t addr) {
    asm volatile("ldmatrix.sync.aligned.m8n8.x4.trans.shared.b16 {%0,%1,%2,%3}, [%4];"
                 : "=r"(r0), "=r"(r1), "=r"(r2), "=r"(r3) : "r"(addr));
}
__device__ __forceinline__ void mma_16816(float* c, uint32_t a0, uint32_t a1, uint32_t a2, uint32_t a3,
                                          uint32_t b0, uint32_t b1) {
    asm volatile("mma.sync.aligned.m16n8k16.row.col.f32.f16.f16.f32 "
                 "{%0,%1,%2,%3},{%4,%5,%6,%7},{%8,%9},{%0,%1,%2,%3};"
                 : "+f"(c[0]), "+f"(c[1]), "+f"(c[2]), "+f"(c[3])
                 : "r"(a0), "r"(a1), "r"(a2), "r"(a3), "r"(b0), "r"(b1));
}

__device__ __forceinline__ void load_edge(const void* ei, int E, int ec, int& j, int& i) {
    if (g_is64) {
        const long long* p = (const long long*)ei;
        j = (int)p[ec]; i = (int)p[(size_t)E + ec];
    } else {
        const int* p = (const int*)ei;
        j = p[ec]; i = p[(size_t)E + ec];
    }
}

// ---------------- kernel 0: fused detect-dtype + zero degrees ----------------
__global__ void k_init(const void* ei, int N) {
    int idx = blockIdx.x * blockDim.x + threadIdx.x;
    if (idx < N) g_deg[idx] = 0;
    if (blockIdx.x == 0 && threadIdx.x < 32) {
        const long long* p = (const long long*)ei;
        long long v = p[threadIdx.x];
        bool ok = (v >= 0 && v < (long long)N);
        unsigned m = __ballot_sync(0xffffffffu, ok);
        if (threadIdx.x == 0) g_is64 = (m == 0xffffffffu) ? 1 : 0;
    }
}

// ---------------- kernel 1: FUSED tensor-core GEMM + edge histogram ----------------
#define A_STRIDE 40    // halves per row (80B, conflict-free ldmatrix)
#define W_STRIDE 136   // halves per row (272B, conflict-free ldmatrix.trans)
__global__ void __launch_bounds__(256) k_gemm_hist(
    const float* __restrict__ x, const float* __restrict__ Wl,
    const float* __restrict__ bl, const float* __restrict__ Wr,
    const float* __restrict__ br, const void* __restrict__ ei,
    int N, int E, int GB)
{
    if (blockIdx.x >= GB) {
        int base = (blockIdx.x - GB) * 1024 + threadIdx.x;
        #pragma unroll
        for (int q = 0; q < 4; q++) {
            int e = base + q * 256;
            if (e < E) {
                int j, i;
                load_edge(ei, E, e, j, i);
                atomicAdd(&g_deg[i], 1);
            }
        }
        return;
    }

    __shared__ __align__(16) __half As[128][A_STRIDE];
    __shared__ __align__(16) __half Ws[32][W_STRIDE];
    __shared__ float bcat[128];

    const int tid = threadIdx.x;
    const int warp = tid >> 5;
    const int lane = tid & 31;
    const int blockM = blockIdx.x * 128;

    if (tid < 128) bcat[tid] = (tid < HC) ? bl[tid] : br[tid - HC];

    float acc[16][4];
    #pragma unroll
    for (int nt = 0; nt < 16; nt++)
        #pragma unroll
        for (int q = 0; q < 4; q++) acc[nt][q] = 0.f;

    for (int k0 = 0; k0 < 128; k0 += 32) {
        #pragma unroll
        for (int it = 0; it < 4; it++) {
            int idx = it * 256 + tid;
            int row = idx >> 3;
            int c4  = (idx & 7) * 4;
            int gm = blockM + row;
            float4 v = make_float4(0.f, 0.f, 0.f, 0.f);
            if (gm < N) v = *reinterpret_cast<const float4*>(&x[(size_t)gm * 128 + k0 + c4]);
            *reinterpret_cast<__half2*>(&As[row][c4])     = __floats2half2_rn(v.x, v.y);
            *reinterpret_cast<__half2*>(&As[row][c4 + 2]) = __floats2half2_rn(v.z, v.w);
        }
        #pragma unroll
        for (int it = 0; it < 4; it++) {
            int idx = it * 256 + tid;
            int kk = idx >> 5;
            int c4 = (idx & 31) * 4;
            int gk = k0 + kk;
            float4 v = (c4 < HC)
                ? *reinterpret_cast<const float4*>(&Wl[(size_t)gk * HC + c4])
                : *reinterpret_cast<const float4*>(&Wr[(size_t)gk * HC + (c4 - HC)]);
            *reinterpret_cast<__half2*>(&Ws[kk][c4])     = __floats2half2_rn(v.x, v.y);
            *reinterpret_cast<__half2*>(&Ws[kk][c4 + 2]) = __floats2half2_rn(v.z, v.w);
        }
        __syncthreads();

        #pragma unroll
        for (int ks = 0; ks < 32; ks += 16) {
            uint32_t a0, a1, a2, a3;
            {
                int g = lane >> 3, r = lane & 7;
                int arow = warp * 16 + ((g & 1) ? 8 : 0) + r;
                int acol = ks + ((g & 2) ? 8 : 0);
                ldmatrix_x4(a0, a1, a2, a3, smem_u32(&As[arow][acol]));
            }
            #pragma unroll
            for (int p = 0; p < 8; p++) {
                int g = lane >> 3, r = lane & 7;
                int krow = ks + ((g & 1) ? 8 : 0) + r;
                int ncol = p * 16 + ((g & 2) ? 8 : 0);
                uint32_t b0, b1, b2, b3;
                ldmatrix_x4_trans(b0, b1, b2, b3, smem_u32(&Ws[krow][ncol]));
                mma_16816(acc[2 * p],     a0, a1, a2, a3, b0, b1);
                mma_16816(acc[2 * p + 1], a0, a1, a2, a3, b2, b3);
            }
        }
        __syncthreads();
    }

    const int crow0 = blockM + warp * 16 + (lane >> 2);
    const int ccol0 = 2 * (lane & 3);
    #pragma unroll
    for (int nt = 0; nt < 16; nt++) {
        int col = nt * 8 + ccol0;
        float bx = bcat[col], by = bcat[col + 1];
        if (crow0 < N)
            *reinterpret_cast<__half2*>(&g_xlr[(size_t)crow0 * ROW + col]) =
                __floats2half2_rn(acc[nt][0] + bx, acc[nt][1] + by);
        if (crow0 + 8 < N)
            *reinterpret_cast<__half2*>(&g_xlr[(size_t)(crow0 + 8) * ROW + col]) =
                __floats2half2_rn(acc[nt][2] + bx, acc[nt][3] + by);
    }
}

// --- scan stage A: per-block local exclusive scan (proven) ---
__global__ void __launch_bounds__(SCAN_BS) kA_scan_local(int N) {
    __shared__ int wt[SCAN_BS / 32];
    const int tid = threadIdx.x, lane = tid & 31, wid = tid >> 5;
    int idx = blockIdx.x * SCAN_BS + tid;
    int v = (idx < N) ? g_deg[idx] : 0;
    int s = v;
    #pragma unroll
    for (int m = 1; m < 32; m <<= 1) {
        int o = __shfl_up_sync(0xffffffffu, s, m);
        if (lane >= m) s += o;
    }
    if (lane == 31) wt[wid] = s;
    __syncthreads();
    if (wid == 0) {
        int w = wt[lane];
        int ws = w;
        #pragma unroll
        for (int m = 1; m < 32; m <<= 1) {
            int o = __shfl_up_sync(0xffffffffu, ws, m);
            if (lane >= m) ws += o;
        }
        wt[lane] = ws - w;   // exclusive warp offsets
    }
    __syncthreads();
    int excl = (s - v) + wt[wid];
    if (idx < N) g_off[idx] = excl;
    if (tid == SCAN_BS - 1) g_blk[blockIdx.x] = excl + v;   // block total
}

// --- scan stage B+C fused: every block redundantly prefix-scans the 98 block
// totals (warp 0, smem), then applies the offset. Removes a serial launch.
__global__ void __launch_bounds__(256) k_scan_final(int N, int NB) {
    __shared__ int pref[NBLK_MAX];
    const int tid = threadIdx.x;
    if (tid < 32) {
        int carry = 0;
        for (int base = 0; base < NB; base += 32) {
            int t = base + tid;
            int v = (t < NB) ? g_blk[t] : 0;
            int s = v;
            #pragma unroll
            for (int m = 1; m < 32; m <<= 1) {
                int o = __shfl_up_sync(0xffffffffu, s, m);
                if (tid >= m) s += o;
            }
            if (t < NB) pref[t] = carry + (s - v);   // exclusive prefix
            carry += __shfl_sync(0xffffffffu, s, 31);
        }
    }
    __syncthreads();
    int idx = blockIdx.x * 256 + tid;
    if (idx < N) {
        int o = g_off[idx] + pref[idx >> 10];
        g_off[idx] = o;
        g_cur[idx] = o;
    }
}

__global__ void k_scatter(const void* __restrict__ ei, int E, int N) {
    int e = blockIdx.x * blockDim.x + threadIdx.x;
    if (e >= E) return;
    int j, i;
    load_edge(ei, E, e, j, i);
    int pos = atomicAdd(&g_cur[i], 1);
    g_src[pos] = j;
}

// ---------------- kernel 2: per-node aggregation (warp per dst node, 2 edges/iter) ----------------
__global__ void __launch_bounds__(256) k_agg(
    const float* __restrict__ att, const float* __restrict__ bias,
    float* __restrict__ out, int N)
{
    const int warp = (blockIdx.x * 256 + threadIdx.x) >> 5;
    const int lane = threadIdx.x & 31;
    if (warp >= N) return;
    const int i = warp;

    const int hl = lane & 15;
    const int cb = hl * 4;
    const bool isA = (lane < 16);

    uint2 bx = *reinterpret_cast<const uint2*>(g_xlr + (size_t)i * ROW + HC + cb);
    float2 b0 = __half22float2(reinterpret_cast<const __half2*>(&bx)[0]);
    float2 b1 = __half22float2(reinterpret_cast<const __half2*>(&bx)[1]);
    float4 t = *reinterpret_cast<const float4*>(&att[cb]);

    float4 acc = make_float4(0.f, 0.f, 0.f, 0.f);
    float d = 0.f;

    auto proc = [&](uint2 ax, bool valid) {
        float2 a0 = __half22float2(reinterpret_cast<const __half2*>(&ax)[0]);
        float2 a1 = __half22float2(reinterpret_cast<const __half2*>(&ax)[1]);
        float s = t.x * lrelu(a0.x + b0.x) + t.y * lrelu(a0.y + b0.y)
                + t.z * lrelu(a1.x + b1.x) + t.w * lrelu(a1.y + b1.y);
        s += __shfl_xor_sync(0xffffffffu, s, 1);
        s += __shfl_xor_sync(0xffffffffu, s, 2);
        s += __shfl_xor_sync(0xffffffffu, s, 4);
        float p = valid ? __expf(s) : 0.f;
        acc.x += p * a0.x; acc.y += p * a0.y;
        acc.z += p * a1.x; acc.w += p * a1.y;
        d += p;
    };

    {
        uint2 ax = *reinterpret_cast<const uint2*>(g_xlr + (size_t)i * ROW + cb);
        proc(ax, isA);
    }

    const int off = g_off[i];
    const int deg = g_deg[i];

    for (int tb = 0; tb < deg; tb += 32) {
        int cnt = deg - tb; if (cnt > 32) cnt = 32;
        int mysrc = (tb + lane < deg) ? g_src[off + tb + lane] : 0;

        int jA = __shfl_sync(0xffffffffu, mysrc, 0);
        int jB = (cnt > 1) ? __shfl_sync(0xffffffffu, mysrc, 1) : jA;
        int j0 = isA ? jA : jB;
        uint2 vcur = *reinterpret_cast<const uint2*>(g_xlr + (size_t)j0 * ROW + cb);

        for (int u = 0; u < cnt; u += 2) {
            uint2 vnext = vcur;
            bool hasNext = (u + 2 < cnt);
            if (hasNext) {
                int nA = __shfl_sync(0xffffffffu, mysrc, u + 2);
                int nB = (u + 3 < cnt) ? __shfl_sync(0xffffffffu, mysrc, u + 3) : nA;
                int nj = isA ? nA : nB;
                vnext = *reinterpret_cast<const uint2*>(g_xlr + (size_t)nj * ROW + cb);
            }
            bool validB = (u + 1 < cnt);
            proc(vcur, isA || validB);
            vcur = vnext;
        }
    }

    acc.x += __shfl_xor_sync(0xffffffffu, acc.x, 16);
    acc.y += __shfl_xor_sync(0xffffffffu, acc.y, 16);
    acc.z += __shfl_xor_sync(0xffffffffu, acc.z, 16);
    acc.w += __shfl_xor_sync(0xffffffffu, acc.w, 16);
    d     += __shfl_xor_sync(0xffffffffu, d, 16);

    float invd = 1.f / (d + 1e-16f);
    float4 v;
    v.x = acc.x * invd; v.y = acc.y * invd; v.z = acc.z * invd; v.w = acc.w * invd;

    float4 o;
    o.x = 0.5f * (v.x + __shfl_xor_sync(0xffffffffu, v.x, 8));
    o.y = 0.5f * (v.y + __shfl_xor_sync(0xffffffffu, v.y, 8));
    o.z = 0.5f * (v.z + __shfl_xor_sync(0xffffffffu, v.z, 8));
    o.w = 0.5f * (v.w + __shfl_xor_sync(0xffffffffu, v.w, 8));

    if (lane < 8) {
        float4 bi = *reinterpret_cast<const float4*>(&bias[cb]);
        o.x += bi.x; o.y += bi.y; o.z += bi.z; o.w += bi.w;
        o.x = o.x / (1.f + expf(-o.x));
        o.y = o.y / (1.f + expf(-o.y));
        o.z = o.z / (1.f + expf(-o.z));
        o.w = o.w / (1.f + expf(-o.w));
        *reinterpret_cast<float4*>(&out[(size_t)i * OUTC + cb]) = o;
    }
}

// ---------------- launch ----------------
extern "C" void kernel_launch(void* const* d_in, const int* in_sizes, int n_in,
                              void* d_out, int out_size) {
    const float* x    = (const float*)d_in[0];
    const float* Wl   = (const float*)d_in[1];
    const float* bl   = (const float*)d_in[2];
    const float* Wr   = (const float*)d_in[3];
    const float* br   = (const float*)d_in[4];
    const float* att  = (const float*)d_in[5];
    const float* bias = (const float*)d_in[6];
    const void*  ei   = (const void*)d_in[7];
    float* out = (float*)d_out;

    int N = in_sizes[0] / 128;   // 100000
    int E = in_sizes[7] / 2;     // 1600000
    int NB = (N + SCAN_BS - 1) / SCAN_BS;   // 98
    int GB = (N + 127) / 128;               // GEMM blocks
    int HB = (E + 1023) / 1024;             // histogram blocks

    k_init<<<(N + 255) / 256, 256>>>(ei, N);
    k_gemm_hist<<<GB + HB, 256>>>(x, Wl, bl, Wr, br, ei, N, E, GB);
    kA_scan_local<<<NB, SCAN_BS>>>(N);
    k_scan_final<<<(N + 255) / 256, 256>>>(N, NB);
    k_scatter<<<(E + 255) / 256, 256>>>(ei, E, N);
    k_agg<<<(N * 32 + 255) / 256, 256>>>(att, bias, out, N);
}